// round 10
// baseline (speedup 1.0000x reference)
#include <cuda_runtime.h>
#include <cuda_bf16.h>
#include <cstdint>

// DCNv2: fused bilinear gather -> bf16 hi/lo split -> mma.sync m16n8k16 GEMM.
// Warp-specialized: warps 0-7 MMA (m32 x n64 tiles), warps 8-15 staging.
// CTA: M=128 outputs x N=128 pixels (2 rows), grid=256, 512 threads.
// K=1152 in 18 chunks of 64, double-buffered smem, 1 syncthreads per chunk.
// 3 MMA passes (hi*hi, hi*lo, lo*hi) accumulate fp32. Fragments via ldmatrix.x4.

#define NTHREADS 512
#define CHUNK_K 64
#define NCHUNK 18
#define LDT 72                       // padded row length (bf16 elems), 144B rows

#define T_WHI 0
#define T_WLO 18432
#define T_SHI 36864
#define T_SLO 55296
#define BUF_BYTES 73728
#define SMEM_BYTES (2 * BUF_BYTES)

#define MMA_BF16(d, a, b)                                                     \
    asm volatile(                                                             \
        "mma.sync.aligned.m16n8k16.row.col.f32.bf16.bf16.f32 "                \
        "{%0,%1,%2,%3}, {%4,%5,%6,%7}, {%8,%9}, {%0,%1,%2,%3};"               \
        : "+f"((d)[0]), "+f"((d)[1]), "+f"((d)[2]), "+f"((d)[3])              \
        : "r"((a)[0]), "r"((a)[1]), "r"((a)[2]), "r"((a)[3]),                 \
          "r"((b)[0]), "r"((b)[1]))

#define LDSM_X4(r, addr)                                                      \
    asm volatile("ldmatrix.sync.aligned.m8n8.x4.shared.b16 {%0,%1,%2,%3}, [%4];" \
                 : "=r"((r)[0]), "=r"((r)[1]), "=r"((r)[2]), "=r"((r)[3])     \
                 : "r"(addr))

__device__ __forceinline__ uint32_t smem_u32(const void* p) {
    uint32_t a;
    asm("{ .reg .u64 t; cvta.to.shared.u64 t, %1; cvt.u32.u64 %0, t; }" : "=r"(a) : "l"(p));
    return a;
}

__global__ void __launch_bounds__(NTHREADS, 1)
dcn_v2_kernel(const float* __restrict__ x,
              const float* __restrict__ offsets,
              const float* __restrict__ mask,
              const float* __restrict__ weight,
              const float* __restrict__ bias,
              float* __restrict__ out) {
    extern __shared__ char smem[];
    const uint32_t sb = smem_u32(smem);

    const int tid  = threadIdx.x;
    const int wid  = tid >> 5;
    const int lane = tid & 31;

    const int bIdx = blockIdx.x >> 5;
    const int h0   = (blockIdx.x & 31) << 1;
    const float* xp = x + ((size_t)bIdx << 19);

    const bool is_stage = (wid >= 8);

    // =============== STAGING STATE (warps 8-15) ===========================
    const int stid  = tid - 256;                 // 0..255 for staging threads
    const int ntaps = is_stage ? (4 + (stid < 128)) : 0;
    uint2  tio[5];
    float4 twt[5];
#pragma unroll
    for (int j = 0; j < 5; ++j) {
        tio[j] = make_uint2(0u, 0u);
        twt[j] = make_float4(0.f, 0.f, 0.f, 0.f);
        if (is_stage && j < ntaps) {
            const int e   = stid + (j << 8);     // 0..1151
            const int t   = e >> 7;              // tap 0..8
            const int pix = e & 127;
            const int h   = h0 + (pix >> 6);
            const int wp  = pix & 63;
            const int ky  = t / 3;
            const int kx  = t - ky * 3;
            const int hw  = (h << 6) + wp;

            const size_t ob = ((size_t)bIdx * 18) << 12;
            const float dy = offsets[ob + ((size_t)(2 * t) << 12) + hw];
            const float dx = offsets[ob + ((size_t)(2 * t + 1) << 12) + hw];
            const float m  = mask[(((size_t)bIdx * 9 + t) << 12) + hw];

            const float py = (float)(h - 1 + ky) + dy;
            const float px = (float)(wp - 1 + kx) + dx;
            const float fy = floorf(py), fx = floorf(px);
            const float ay = py - fy, ax = px - fx;
            const float by = 1.f - ay, bx = 1.f - ax;
            const float fy1 = fy + 1.f, fx1 = fx + 1.f;
            const bool vy0 = (fy  >= 0.f) && (fy  <= 63.f);
            const bool vy1 = (fy1 >= 0.f) && (fy1 <= 63.f);
            const bool vx0 = (fx  >= 0.f) && (fx  <= 63.f);
            const bool vx1 = (fx1 >= 0.f) && (fx1 <= 63.f);
            const int y0 = (int)fminf(fmaxf(fy,  0.f), 63.f);
            const int y1 = (int)fminf(fmaxf(fy1, 0.f), 63.f);
            const int x0 = (int)fminf(fmaxf(fx,  0.f), 63.f);
            const int x1 = (int)fminf(fmaxf(fx1, 0.f), 63.f);
            const unsigned i0 = (unsigned)((y0 << 6) + x0);
            const unsigned i1 = (unsigned)((y0 << 6) + x1);
            const unsigned i2 = (unsigned)((y1 << 6) + x0);
            const unsigned i3 = (unsigned)((y1 << 6) + x1);
            tio[j] = make_uint2(i0 | (i1 << 16), i2 | (i3 << 16));
            twt[j] = make_float4((vy0 && vx0) ? by * bx * m : 0.f,
                                 (vy0 && vx1) ? by * ax * m : 0.f,
                                 (vy1 && vx0) ? ay * bx * m : 0.f,
                                 (vy1 && vx1) ? ay * ax * m : 0.f);
        }
    }

#define STAGE_W(BUF, K0)                                                      \
    do {                                                                      \
        char* dhi = smem + (BUF) * BUF_BYTES + T_WHI;                         \
        char* dlo = smem + (BUF) * BUF_BYTES + T_WLO;                         \
        _Pragma("unroll")                                                     \
        for (int it = 0; it < 8; ++it) {                                      \
            const int idx4 = stid + it * 256;                                 \
            const int o  = idx4 >> 4;                                         \
            const int kq = idx4 & 15;                                         \
            const float4 f = __ldg(                                           \
                (const float4*)(weight + (size_t)o * 1152 + (K0) + kq * 4));  \
            __nv_bfloat162 h01 = __floats2bfloat162_rn(f.x, f.y);             \
            __nv_bfloat162 h23 = __floats2bfloat162_rn(f.z, f.w);             \
            const float2 g01 = __bfloat1622float2(h01);                       \
            const float2 g23 = __bfloat1622float2(h23);                       \
            __nv_bfloat162 l01 = __floats2bfloat162_rn(f.x - g01.x, f.y - g01.y); \
            __nv_bfloat162 l23 = __floats2bfloat162_rn(f.z - g23.x, f.w - g23.y); \
            const int bo = o * (LDT * 2) + kq * 8;                            \
            *(uint2*)(dhi + bo) = make_uint2(*(uint32_t*)&h01, *(uint32_t*)&h23); \
            *(uint2*)(dlo + bo) = make_uint2(*(uint32_t*)&l01, *(uint32_t*)&l23); \
        }                                                                     \
    } while (0)

#define STAGE_S(BUF, K0)                                                      \
    do {                                                                      \
        __nv_bfloat16* dhi = (__nv_bfloat16*)(smem + (BUF) * BUF_BYTES + T_SHI); \
        __nv_bfloat16* dlo = (__nv_bfloat16*)(smem + (BUF) * BUF_BYTES + T_SLO); \
        _Pragma("unroll")                                                     \
        for (int j = 0; j < 5; ++j) {                                         \
            if (j < ntaps) {                                                  \
                const int e   = stid + (j << 8);                              \
                const int t   = e >> 7;                                       \
                const int pix = e & 127;                                      \
                const int i0 = tio[j].x & 0xFFFF, i1 = tio[j].x >> 16;        \
                const int i2 = tio[j].y & 0xFFFF, i3 = tio[j].y >> 16;        \
                const float4 w = twt[j];                                      \
                int c = ((K0) - t + 8) / 9;                                   \
                const int cend = ((K0) + 63 - t) / 9;                         \
                for (; c <= cend; ++c) {                                      \
                    const float* p = xp + ((size_t)c << 12);                  \
                    const float v = fmaf(w.x, __ldg(p + i0),                  \
                                    fmaf(w.y, __ldg(p + i1),                  \
                                    fmaf(w.z, __ldg(p + i2),                  \
                                         w.w * __ldg(p + i3))));              \
                    const __nv_bfloat16 hb = __float2bfloat16(v);             \
                    const __nv_bfloat16 lb =                                  \
                        __float2bfloat16(v - __bfloat162float(hb));           \
                    const int kl = c * 9 + t - (K0);                          \
                    dhi[pix * LDT + kl] = hb;                                 \
                    dlo[pix * LDT + kl] = lb;                                 \
                }                                                             \
            }                                                                 \
        }                                                                     \
    } while (0)

    // =============== MMA STATE (warps 0-7) ================================
    const int wm = wid >> 1;         // 0..3  (m block of 32)
    const int wn = wid & 1;          // 0..1  (n block of 64)
    const int grp = lane >> 2;
    const int qp  = lane & 3;

    float acc[2][8][4];
#pragma unroll
    for (int mi = 0; mi < 2; ++mi)
#pragma unroll
        for (int ni = 0; ni < 8; ++ni)
#pragma unroll
            for (int q = 0; q < 4; ++q) acc[mi][ni][q] = 0.f;

    // per-lane ldmatrix row addressing (constant parts)
    const int lr   = lane >> 3;      // matrix index 0..3
    const int lrow = lane & 7;       // row within matrix
    // A: matrix r -> m += (r&1)*8, k += (r>>1)*8
    const uint32_t a_lane_off =
        (uint32_t)(((wm * 32 + (lr & 1) * 8 + lrow) * LDT + (lr >> 1) * 8) * 2);
    // B: matrices {0,1}=hi (k,k+8), {2,3}=lo (k,k+8)
    const uint32_t b_lane_off =
        (uint32_t)(((wn * 64 + lrow) * LDT + (lr & 1) * 8) * 2) +
        (uint32_t)((lr >> 1) ? T_SLO : T_SHI);

    // =============== prologue =============================================
    if (is_stage) { STAGE_W(0, 0); STAGE_S(0, 0); }
    __syncthreads();

    // =============== main loop ============================================
    for (int ch = 0; ch < NCHUNK; ++ch) {
        const int cur = ch & 1;
        if (is_stage) {
            if (ch + 1 < NCHUNK) {
                const int k0n = (ch + 1) * CHUNK_K;
                STAGE_W(cur ^ 1, k0n);
                STAGE_S(cur ^ 1, k0n);
            }
        } else {
            const uint32_t bufb = sb + cur * BUF_BYTES;
            const uint32_t whi = bufb + T_WHI + a_lane_off;
            const uint32_t wlo = bufb + T_WLO + a_lane_off;
            const uint32_t bba = bufb + b_lane_off;
#pragma unroll
            for (int ks = 0; ks < 4; ++ks) {
                uint32_t ahi[2][4], alo[2][4];
#pragma unroll
                for (int mi = 0; mi < 2; ++mi) {
                    LDSM_X4(ahi[mi], whi + (uint32_t)((mi * 16 * LDT + ks * 16) * 2));
                    LDSM_X4(alo[mi], wlo + (uint32_t)((mi * 16 * LDT + ks * 16) * 2));
                }
#pragma unroll
                for (int ni = 0; ni < 8; ++ni) {
                    uint32_t b4[4];   // {hi k0, hi k8, lo k0, lo k8}
                    LDSM_X4(b4, bba + (uint32_t)((ni * 8 * LDT + ks * 16) * 2));
#pragma unroll
                    for (int mi = 0; mi < 2; ++mi) {
                        MMA_BF16(acc[mi][ni], ahi[mi], b4);       // hi*hi
                        MMA_BF16(acc[mi][ni], ahi[mi], b4 + 2);   // hi*lo
                        MMA_BF16(acc[mi][ni], alo[mi], b4);       // lo*hi
                    }
                }
            }
        }
        __syncthreads();
    }

    // =============== epilogue (MMA warps only) ============================
    if (!is_stage) {
#pragma unroll
        for (int mi = 0; mi < 2; ++mi) {
#pragma unroll
            for (int half = 0; half < 2; ++half) {
                const int o = wm * 32 + mi * 16 + grp + half * 8;
                const float bi = __ldg(bias + o);
                float* po = out + (((size_t)bIdx * 128 + o) << 12) + (h0 << 6);
#pragma unroll
                for (int ni = 0; ni < 8; ++ni) {
                    const int n = wn * 64 + ni * 8 + qp * 2;
                    float2 v;
                    v.x = acc[mi][ni][half * 2 + 0] + bi;
                    v.y = acc[mi][ni][half * 2 + 1] + bi;
                    *(float2*)(po + n) = v;
                }
            }
        }
    }
}

extern "C" void kernel_launch(void* const* d_in, const int* in_sizes, int n_in,
                              void* d_out, int out_size) {
    const float* x       = (const float*)d_in[0];
    const float* offsets = (const float*)d_in[1];
    const float* mask    = (const float*)d_in[2];
    const float* weight  = (const float*)d_in[3];
    const float* bias    = (const float*)d_in[4];
    float* out = (float*)d_out;

    cudaFuncSetAttribute(dcn_v2_kernel,
                         cudaFuncAttributeMaxDynamicSharedMemorySize, SMEM_BYTES);

    dcn_v2_kernel<<<256, NTHREADS, SMEM_BYTES>>>(x, offsets, mask, weight, bias, out);
}

// round 11
// speedup vs baseline: 1.2173x; 1.2173x over previous
#include <cuda_runtime.h>
#include <cuda_bf16.h>
#include <cstdint>

// DCNv2: fused bilinear gather -> bf16 hi/lo split -> mma.sync m16n8k16 GEMM.
// Homogeneous warps (R9 structure): all 16 warps stage then MMA, double buffer.
// CTA: M=128 outputs x N=128 pixels, grid=256, 512 threads, 4x4 warp grid m32n32.
// K=1152 in 18 chunks of 64. 3 MMA passes (hi*hi,hi*lo,lo*hi) -> ~fp32 accuracy.
// R11: constant-trip unrolled gather (MLP ~16) + ldmatrix.x4 fragment loads.

#define NTHREADS 512
#define CHUNK_K 64
#define NCHUNK 18
#define LDT 72                       // padded row length (bf16), 144B rows

#define T_WHI 0
#define T_WLO 18432
#define T_SHI 36864
#define T_SLO 55296
#define BUF_BYTES 73728
#define SMEM_BYTES (2 * BUF_BYTES)

#define MMA_BF16(d, a, b)                                                     \
    asm volatile(                                                             \
        "mma.sync.aligned.m16n8k16.row.col.f32.bf16.bf16.f32 "                \
        "{%0,%1,%2,%3}, {%4,%5,%6,%7}, {%8,%9}, {%0,%1,%2,%3};"               \
        : "+f"((d)[0]), "+f"((d)[1]), "+f"((d)[2]), "+f"((d)[3])              \
        : "r"((a)[0]), "r"((a)[1]), "r"((a)[2]), "r"((a)[3]),                 \
          "r"((b)[0]), "r"((b)[1]))

#define LDSM_X4(r, addr)                                                      \
    asm volatile("ldmatrix.sync.aligned.m8n8.x4.shared.b16 {%0,%1,%2,%3}, [%4];" \
                 : "=r"((r)[0]), "=r"((r)[1]), "=r"((r)[2]), "=r"((r)[3])     \
                 : "r"(addr))

__device__ __forceinline__ uint32_t smem_u32(const void* p) {
    uint32_t a;
    asm("{ .reg .u64 t; cvta.to.shared.u64 t, %1; cvt.u32.u64 %0, t; }" : "=r"(a) : "l"(p));
    return a;
}

__global__ void __launch_bounds__(NTHREADS, 1)
dcn_v2_kernel(const float* __restrict__ x,
              const float* __restrict__ offsets,
              const float* __restrict__ mask,
              const float* __restrict__ weight,
              const float* __restrict__ bias,
              float* __restrict__ out) {
    extern __shared__ char smem[];
    const uint32_t sb = smem_u32(smem);

    const int tid  = threadIdx.x;
    const int wid  = tid >> 5;
    const int lane = tid & 31;
    const int grp  = lane >> 2;
    const int qp   = lane & 3;
    const int wm   = wid >> 2;       // warp m-group 0..3
    const int wn   = wid & 3;        // warp n-group 0..3

    const int bIdx = blockIdx.x >> 5;
    const int h0   = (blockIdx.x & 31) << 1;
    const float* xp = x + ((size_t)bIdx << 19);

    // ---- register-resident bilinear taps (1152 = 9 taps x 128 pixels) ----
    const int ntaps = 2 + (tid < 128);
    uint2  tio[3];
    float4 twt[3];
#pragma unroll
    for (int j = 0; j < 3; ++j) {
        tio[j] = make_uint2(0u, 0u);
        twt[j] = make_float4(0.f, 0.f, 0.f, 0.f);
        if (j < ntaps) {
            const int e   = tid + (j << 9);
            const int t   = e >> 7;
            const int pix = e & 127;
            const int h   = h0 + (pix >> 6);
            const int wp  = pix & 63;
            const int ky  = t / 3;
            const int kx  = t - ky * 3;
            const int hw  = (h << 6) + wp;

            const size_t ob = ((size_t)bIdx * 18) << 12;
            const float dy = offsets[ob + ((size_t)(2 * t) << 12) + hw];
            const float dx = offsets[ob + ((size_t)(2 * t + 1) << 12) + hw];
            const float m  = mask[(((size_t)bIdx * 9 + t) << 12) + hw];

            const float py = (float)(h - 1 + ky) + dy;
            const float px = (float)(wp - 1 + kx) + dx;
            const float fy = floorf(py), fx = floorf(px);
            const float ay = py - fy, ax = px - fx;
            const float by = 1.f - ay, bx = 1.f - ax;
            const float fy1 = fy + 1.f, fx1 = fx + 1.f;
            const bool vy0 = (fy  >= 0.f) && (fy  <= 63.f);
            const bool vy1 = (fy1 >= 0.f) && (fy1 <= 63.f);
            const bool vx0 = (fx  >= 0.f) && (fx  <= 63.f);
            const bool vx1 = (fx1 >= 0.f) && (fx1 <= 63.f);
            const int y0 = (int)fminf(fmaxf(fy,  0.f), 63.f);
            const int y1 = (int)fminf(fmaxf(fy1, 0.f), 63.f);
            const int x0 = (int)fminf(fmaxf(fx,  0.f), 63.f);
            const int x1 = (int)fminf(fmaxf(fx1, 0.f), 63.f);
            const unsigned i0 = (unsigned)((y0 << 6) + x0);
            const unsigned i1 = (unsigned)((y0 << 6) + x1);
            const unsigned i2 = (unsigned)((y1 << 6) + x0);
            const unsigned i3 = (unsigned)((y1 << 6) + x1);
            tio[j] = make_uint2(i0 | (i1 << 16), i2 | (i3 << 16));
            twt[j] = make_float4((vy0 && vx0) ? by * bx * m : 0.f,
                                 (vy0 && vx1) ? by * ax * m : 0.f,
                                 (vy1 && vx0) ? ay * bx * m : 0.f,
                                 (vy1 && vx1) ? ay * ax * m : 0.f);
        }
    }

    float acc[2][4][4];
#pragma unroll
    for (int mi = 0; mi < 2; ++mi)
#pragma unroll
        for (int ni = 0; ni < 4; ++ni)
#pragma unroll
            for (int q = 0; q < 4; ++q) acc[mi][ni][q] = 0.f;

    // ---- staging helpers ----
#define STAGE_W(BUF, K0)                                                      \
    do {                                                                      \
        char* dhi = smem + (BUF) * BUF_BYTES + T_WHI;                         \
        char* dlo = smem + (BUF) * BUF_BYTES + T_WLO;                         \
        _Pragma("unroll")                                                     \
        for (int it = 0; it < 4; ++it) {                                      \
            const int idx4 = tid + it * NTHREADS;                             \
            const int o  = idx4 >> 4;                                         \
            const int kq = idx4 & 15;                                         \
            const float4 f = __ldg(                                           \
                (const float4*)(weight + (size_t)o * 1152 + (K0) + kq * 4));  \
            __nv_bfloat162 h01 = __floats2bfloat162_rn(f.x, f.y);             \
            __nv_bfloat162 h23 = __floats2bfloat162_rn(f.z, f.w);             \
            const float2 g01 = __bfloat1622float2(h01);                       \
            const float2 g23 = __bfloat1622float2(h23);                       \
            __nv_bfloat162 l01 = __floats2bfloat162_rn(f.x - g01.x, f.y - g01.y); \
            __nv_bfloat162 l23 = __floats2bfloat162_rn(f.z - g23.x, f.w - g23.y); \
            const int bo = o * (LDT * 2) + kq * 8;                            \
            *(uint2*)(dhi + bo) = make_uint2(*(uint32_t*)&h01, *(uint32_t*)&h23); \
            *(uint2*)(dlo + bo) = make_uint2(*(uint32_t*)&l01, *(uint32_t*)&l23); \
        }                                                                     \
    } while (0)

    // Constant-trip gather: 8 unrolled channel steps per tap, STS predicated.
#define STAGE_S(BUF, K0)                                                      \
    do {                                                                      \
        __nv_bfloat16* dhi = (__nv_bfloat16*)(smem + (BUF) * BUF_BYTES + T_SHI); \
        __nv_bfloat16* dlo = (__nv_bfloat16*)(smem + (BUF) * BUF_BYTES + T_SLO); \
        _Pragma("unroll")                                                     \
        for (int j = 0; j < 3; ++j) {                                         \
            if (j < ntaps) {                                                  \
                const int e   = tid + (j << 9);                               \
                const int t   = e >> 7;                                       \
                const int pix = e & 127;                                      \
                const int i0 = tio[j].x & 0xFFFF, i1 = tio[j].x >> 16;        \
                const int i2 = tio[j].y & 0xFFFF, i3 = tio[j].y >> 16;        \
                const float4 w = twt[j];                                      \
                const int cbase = ((K0) - t + 8) / 9;                         \
                const int kl0   = cbase * 9 + t - (K0);                       \
                _Pragma("unroll")                                             \
                for (int uu = 0; uu < 2; ++uu) {                              \
                    float v[4];                                               \
                    _Pragma("unroll")                                         \
                    for (int u = 0; u < 4; ++u) {                             \
                        const int c = cbase + uu * 4 + u;                     \
                        const int cc = (c < 127) ? c : 127;                   \
                        const float* p = xp + ((size_t)cc << 12);             \
                        v[u] = fmaf(w.x, __ldg(p + i0),                       \
                               fmaf(w.y, __ldg(p + i1),                       \
                               fmaf(w.z, __ldg(p + i2),                       \
                                    w.w * __ldg(p + i3))));                   \
                    }                                                         \
                    _Pragma("unroll")                                         \
                    for (int u = 0; u < 4; ++u) {                             \
                        const int kl = kl0 + (uu * 4 + u) * 9;                \
                        if (kl < CHUNK_K) {                                   \
                            const __nv_bfloat16 hb = __float2bfloat16(v[u]);  \
                            const __nv_bfloat16 lb =                          \
                                __float2bfloat16(v[u] - __bfloat162float(hb)); \
                            dhi[pix * LDT + kl] = hb;                         \
                            dlo[pix * LDT + kl] = lb;                         \
                        }                                                     \
                    }                                                         \
                }                                                             \
            }                                                                 \
        }                                                                     \
    } while (0)

    // ---- ldmatrix lane addressing (constant parts) ----
    const int lr   = lane >> 3;      // matrix index 0..3
    const int lrow = lane & 7;       // row within matrix
    // A x4: m0: rows 0-7 k0, m1: rows 8-15 k0, m2: rows 0-7 k8, m3: rows 8-15 k8
    const uint32_t a_lane_off =
        (uint32_t)(((wm * 32 + (lr & 1) * 8 + lrow) * LDT + (lr >> 1) * 8) * 2);
    // B x4: m0: hi k0, m1: hi k8, m2: lo k0, m3: lo k8 (8 n-rows each)
    const uint32_t b_lane_off =
        (uint32_t)(((wn * 32 + lrow) * LDT + (lr & 1) * 8) * 2) +
        (uint32_t)((lr >> 1) ? T_SLO : T_SHI);

    // ---- prologue ----
    STAGE_W(0, 0);
    STAGE_S(0, 0);
    __syncthreads();

    // ---- main loop: stage(next) then mma(current), one sync/chunk --------
    for (int ch = 0; ch < NCHUNK; ++ch) {
        const int cur = ch & 1;
        if (ch + 1 < NCHUNK) {
            const int k0n = (ch + 1) * CHUNK_K;
            STAGE_W(cur ^ 1, k0n);
            STAGE_S(cur ^ 1, k0n);
        }

        const uint32_t bufb = sb + cur * BUF_BYTES;
        const uint32_t whi = bufb + T_WHI + a_lane_off;
        const uint32_t wlo = bufb + T_WLO + a_lane_off;
        const uint32_t bba = bufb + b_lane_off;
#pragma unroll
        for (int ks = 0; ks < 4; ++ks) {
            uint32_t ahi[2][4], alo[2][4];
#pragma unroll
            for (int mi = 0; mi < 2; ++mi) {
                LDSM_X4(ahi[mi], whi + (uint32_t)((mi * 16 * LDT + ks * 16) * 2));
                LDSM_X4(alo[mi], wlo + (uint32_t)((mi * 16 * LDT + ks * 16) * 2));
            }
#pragma unroll
            for (int ni = 0; ni < 4; ++ni) {
                uint32_t b4[4];   // {hi k0, hi k8, lo k0, lo k8}
                LDSM_X4(b4, bba + (uint32_t)((ni * 8 * LDT + ks * 16) * 2));
#pragma unroll
                for (int mi = 0; mi < 2; ++mi) {
                    MMA_BF16(acc[mi][ni], ahi[mi], b4);       // hi*hi
                    MMA_BF16(acc[mi][ni], ahi[mi], b4 + 2);   // hi*lo
                    MMA_BF16(acc[mi][ni], alo[mi], b4);       // lo*hi
                }
            }
        }
        __syncthreads();
    }

    // ---- epilogue: + bias, float2 stores ---------------------------------
#pragma unroll
    for (int mi = 0; mi < 2; ++mi) {
#pragma unroll
        for (int half = 0; half < 2; ++half) {
            const int o = wm * 32 + mi * 16 + grp + half * 8;
            const float bi = __ldg(bias + o);
            float* po = out + (((size_t)bIdx * 128 + o) << 12) + (h0 << 6);
#pragma unroll
            for (int ni = 0; ni < 4; ++ni) {
                const int n = wn * 32 + ni * 8 + qp * 2;
                float2 v;
                v.x = acc[mi][ni][half * 2 + 0] + bi;
                v.y = acc[mi][ni][half * 2 + 1] + bi;
                *(float2*)(po + n) = v;
            }
        }
    }
}

extern "C" void kernel_launch(void* const* d_in, const int* in_sizes, int n_in,
                              void* d_out, int out_size) {
    const float* x       = (const float*)d_in[0];
    const float* offsets = (const float*)d_in[1];
    const float* mask    = (const float*)d_in[2];
    const float* weight  = (const float*)d_in[3];
    const float* bias    = (const float*)d_in[4];
    float* out = (float*)d_out;

    cudaFuncSetAttribute(dcn_v2_kernel,
                         cudaFuncAttributeMaxDynamicSharedMemorySize, SMEM_BYTES);

    dcn_v2_kernel<<<256, NTHREADS, SMEM_BYTES>>>(x, offsets, mask, weight, bias, out);
}

// round 12
// speedup vs baseline: 1.2821x; 1.0532x over previous
#include <cuda_runtime.h>
#include <cuda_bf16.h>
#include <cstdint>

// DCNv2: fused bilinear gather -> bf16 hi/lo split -> mma.sync m16n8k16 GEMM.
// R12: k-major swizzled S tile (conflict-free STS + ldmatrix.trans for B) and
// intra-warp software pipeline (gather || MMA within each chunk).
// CTA: M=128 outputs x N=128 pixels, grid=256, 512 threads, 4x4 warps m32n32.
// K=1152 in 18 chunks of 64. 3 MMA passes (hi*hi,hi*lo,lo*hi) ~ fp32 accuracy.

#define NTHREADS 512
#define CHUNK_K 64
#define NCHUNK 18
#define LDT 72                       // W tile row length (bf16), 144B rows

#define T_WHI 0                      // W hi: 128 x 72 bf16 = 18432 B
#define T_WLO 18432                  // W lo
#define T_SHI 36864                  // S hi: 64 x 128 bf16 (k-major) = 16384 B
#define T_SLO 53248                  // S lo
#define BUF_BYTES 69632
#define SMEM_BYTES (2 * BUF_BYTES)

#define MMA_BF16(d, a, b)                                                     \
    asm volatile(                                                             \
        "mma.sync.aligned.m16n8k16.row.col.f32.bf16.bf16.f32 "                \
        "{%0,%1,%2,%3}, {%4,%5,%6,%7}, {%8,%9}, {%0,%1,%2,%3};"               \
        : "+f"((d)[0]), "+f"((d)[1]), "+f"((d)[2]), "+f"((d)[3])              \
        : "r"((a)[0]), "r"((a)[1]), "r"((a)[2]), "r"((a)[3]),                 \
          "r"((b)[0]), "r"((b)[1]))

#define LDSM_X4(r, addr)                                                      \
    asm volatile("ldmatrix.sync.aligned.m8n8.x4.shared.b16 {%0,%1,%2,%3}, [%4];" \
                 : "=r"((r)[0]), "=r"((r)[1]), "=r"((r)[2]), "=r"((r)[3])     \
                 : "r"(addr))

#define LDSM_X4T(r, addr)                                                     \
    asm volatile("ldmatrix.sync.aligned.m8n8.x4.trans.shared.b16 {%0,%1,%2,%3}, [%4];" \
                 : "=r"((r)[0]), "=r"((r)[1]), "=r"((r)[2]), "=r"((r)[3])     \
                 : "r"(addr))

__device__ __forceinline__ uint32_t smem_u32(const void* p) {
    uint32_t a;
    asm("{ .reg .u64 t; cvta.to.shared.u64 t, %1; cvt.u32.u64 %0, t; }" : "=r"(a) : "l"(p));
    return a;
}

__global__ void __launch_bounds__(NTHREADS, 1)
dcn_v2_kernel(const float* __restrict__ x,
              const float* __restrict__ offsets,
              const float* __restrict__ mask,
              const float* __restrict__ weight,
              const float* __restrict__ bias,
              float* __restrict__ out) {
    extern __shared__ char smem[];
    const uint32_t sb = smem_u32(smem);

    const int tid  = threadIdx.x;
    const int wid  = tid >> 5;
    const int lane = tid & 31;
    const int grp  = lane >> 2;
    const int qp   = lane & 3;
    const int wm   = wid >> 2;
    const int wn   = wid & 3;

    const int bIdx = blockIdx.x >> 5;
    const int h0   = (blockIdx.x & 31) << 1;
    const float* xp = x + ((size_t)bIdx << 19);

    // ---- register-resident bilinear taps ---------------------------------
    const int ntaps = 2 + (tid < 128);
    uint2  tio[3];
    float4 twt[3];
#pragma unroll
    for (int j = 0; j < 3; ++j) {
        tio[j] = make_uint2(0u, 0u);
        twt[j] = make_float4(0.f, 0.f, 0.f, 0.f);
        if (j < ntaps) {
            const int e   = tid + (j << 9);
            const int t   = e >> 7;
            const int pix = e & 127;
            const int h   = h0 + (pix >> 6);
            const int wp  = pix & 63;
            const int ky  = t / 3;
            const int kx  = t - ky * 3;
            const int hw  = (h << 6) + wp;

            const size_t ob = ((size_t)bIdx * 18) << 12;
            const float dy = offsets[ob + ((size_t)(2 * t) << 12) + hw];
            const float dx = offsets[ob + ((size_t)(2 * t + 1) << 12) + hw];
            const float m  = mask[(((size_t)bIdx * 9 + t) << 12) + hw];

            const float py = (float)(h - 1 + ky) + dy;
            const float px = (float)(wp - 1 + kx) + dx;
            const float fy = floorf(py), fx = floorf(px);
            const float ay = py - fy, ax = px - fx;
            const float by = 1.f - ay, bx = 1.f - ax;
            const float fy1 = fy + 1.f, fx1 = fx + 1.f;
            const bool vy0 = (fy  >= 0.f) && (fy  <= 63.f);
            const bool vy1 = (fy1 >= 0.f) && (fy1 <= 63.f);
            const bool vx0 = (fx  >= 0.f) && (fx  <= 63.f);
            const bool vx1 = (fx1 >= 0.f) && (fx1 <= 63.f);
            const int y0 = (int)fminf(fmaxf(fy,  0.f), 63.f);
            const int y1 = (int)fminf(fmaxf(fy1, 0.f), 63.f);
            const int x0 = (int)fminf(fmaxf(fx,  0.f), 63.f);
            const int x1 = (int)fminf(fmaxf(fx1, 0.f), 63.f);
            const unsigned i0 = (unsigned)((y0 << 6) + x0);
            const unsigned i1 = (unsigned)((y0 << 6) + x1);
            const unsigned i2 = (unsigned)((y1 << 6) + x0);
            const unsigned i3 = (unsigned)((y1 << 6) + x1);
            tio[j] = make_uint2(i0 | (i1 << 16), i2 | (i3 << 16));
            twt[j] = make_float4((vy0 && vx0) ? by * bx * m : 0.f,
                                 (vy0 && vx1) ? by * ax * m : 0.f,
                                 (vy1 && vx0) ? ay * bx * m : 0.f,
                                 (vy1 && vx1) ? ay * ax * m : 0.f);
        }
    }

    float acc[2][4][4];
#pragma unroll
    for (int mi = 0; mi < 2; ++mi)
#pragma unroll
        for (int ni = 0; ni < 4; ++ni)
#pragma unroll
            for (int q = 0; q < 4; ++q) acc[mi][ni][q] = 0.f;

    // ---- staging helpers --------------------------------------------------
    // gather 4 channels (U0..U0+3) of each owned tap into V
#define GATHER_HALF(V, K0N, U0)                                               \
    do {                                                                      \
        _Pragma("unroll")                                                     \
        for (int j = 0; j < 3; ++j) {                                         \
            if (j < ntaps) {                                                  \
                const int e = tid + (j << 9);                                 \
                const int t = e >> 7;                                         \
                const int i0 = tio[j].x & 0xFFFF, i1 = tio[j].x >> 16;        \
                const int i2 = tio[j].y & 0xFFFF, i3 = tio[j].y >> 16;        \
                const float4 w = twt[j];                                      \
                const int cbase = ((K0N) - t + 8) / 9;                        \
                _Pragma("unroll")                                             \
                for (int u = 0; u < 4; ++u) {                                 \
                    const int c = cbase + (U0) + u;                           \
                    const int cc = (c < 127) ? c : 127;                       \
                    const float* p = xp + ((size_t)cc << 12);                 \
                    V[j][u] = fmaf(w.x, __ldg(p + i0),                        \
                              fmaf(w.y, __ldg(p + i1),                        \
                              fmaf(w.z, __ldg(p + i2),                        \
                                   w.w * __ldg(p + i3))));                    \
                }                                                             \
            }                                                                 \
        }                                                                     \
    } while (0)

    // convert + store to swizzled k-major S tiles
#define COMMIT_HALF(V, BUFB_HOST, K0N, U0)                                    \
    do {                                                                      \
        char* shi = smem + (BUFB_HOST) + T_SHI;                               \
        char* slo = smem + (BUFB_HOST) + T_SLO;                               \
        _Pragma("unroll")                                                     \
        for (int j = 0; j < 3; ++j) {                                         \
            if (j < ntaps) {                                                  \
                const int e   = tid + (j << 9);                               \
                const int t   = e >> 7;                                       \
                const int pix = e & 127;                                      \
                const int cbase = ((K0N) - t + 8) / 9;                        \
                const int kl0   = cbase * 9 + t - (K0N);                      \
                _Pragma("unroll")                                             \
                for (int u = 0; u < 4; ++u) {                                 \
                    const int kl = kl0 + ((U0) + u) * 9;                      \
                    if (kl < CHUNK_K) {                                       \
                        const float v = V[j][u];                              \
                        const __nv_bfloat16 hb = __float2bfloat16(v);         \
                        const __nv_bfloat16 lb =                              \
                            __float2bfloat16(v - __bfloat162float(hb));       \
                        const int ad = kl * 256 + ((pix * 2) ^ ((kl & 7) << 4)); \
                        *(__nv_bfloat16*)(shi + ad) = hb;                     \
                        *(__nv_bfloat16*)(slo + ad) = lb;                     \
                    }                                                         \
                }                                                             \
            }                                                                 \
        }                                                                     \
    } while (0)

#define W_LOAD(WF, K0N, IT0)                                                  \
    do {                                                                      \
        _Pragma("unroll")                                                     \
        for (int it = 0; it < 2; ++it) {                                      \
            const int idx4 = tid + ((IT0) + it) * NTHREADS;                   \
            const int o  = idx4 >> 4;                                         \
            const int kq = idx4 & 15;                                         \
            WF[it] = __ldg(                                                   \
                (const float4*)(weight + (size_t)o * 1152 + (K0N) + kq * 4)); \
        }                                                                     \
    } while (0)

#define W_COMMIT(WF, BUFB_HOST, IT0)                                          \
    do {                                                                      \
        char* dhi = smem + (BUFB_HOST) + T_WHI;                               \
        char* dlo = smem + (BUFB_HOST) + T_WLO;                               \
        _Pragma("unroll")                                                     \
        for (int it = 0; it < 2; ++it) {                                      \
            const int idx4 = tid + ((IT0) + it) * NTHREADS;                   \
            const int o  = idx4 >> 4;                                         \
            const int kq = idx4 & 15;                                         \
            const float4 f = WF[it];                                          \
            __nv_bfloat162 h01 = __floats2bfloat162_rn(f.x, f.y);             \
            __nv_bfloat162 h23 = __floats2bfloat162_rn(f.z, f.w);             \
            const float2 g01 = __bfloat1622float2(h01);                       \
            const float2 g23 = __bfloat1622float2(h23);                       \
            __nv_bfloat162 l01 = __floats2bfloat162_rn(f.x - g01.x, f.y - g01.y); \
            __nv_bfloat162 l23 = __floats2bfloat162_rn(f.z - g23.x, f.w - g23.y); \
            const int bo = o * (LDT * 2) + kq * 8;                            \
            *(uint2*)(dhi + bo) = make_uint2(*(uint32_t*)&h01, *(uint32_t*)&h23); \
            *(uint2*)(dlo + bo) = make_uint2(*(uint32_t*)&l01, *(uint32_t*)&l23); \
        }                                                                     \
    } while (0)

    // ---- MMA lane addressing ----------------------------------------------
    const int lr   = lane >> 3;
    const int lrow = lane & 7;
    const uint32_t a_lane_off =
        (uint32_t)(((wm * 32 + (lr & 1) * 8 + lrow) * LDT + (lr >> 1) * 8) * 2);
    // B (k-major swizzled): matrices {hi k+0, hi k+8, lo k+0, lo k+8}
    const uint32_t b_lane_const =
        (uint32_t)(((lr & 1) * 8 + lrow) * 256) + (uint32_t)((lr >> 1) ? T_SLO : T_SHI);
    const uint32_t xorv = (uint32_t)(lrow << 4);
    const uint32_t wn64 = (uint32_t)(wn * 64);

#define MMA_HALF(BUFB, KS0)                                                   \
    do {                                                                      \
        const uint32_t whiA = (BUFB) + T_WHI + a_lane_off;                    \
        const uint32_t wloA = (BUFB) + T_WLO + a_lane_off;                    \
        const uint32_t bB   = (BUFB) + b_lane_const;                          \
        _Pragma("unroll")                                                     \
        for (int ks = (KS0); ks < (KS0) + 2; ++ks) {                          \
            uint32_t ahi[2][4], alo[2][4];                                    \
            _Pragma("unroll")                                                 \
            for (int mi = 0; mi < 2; ++mi) {                                  \
                LDSM_X4(ahi[mi], whiA + (uint32_t)((mi * 16 * LDT + ks * 16) * 2)); \
                LDSM_X4(alo[mi], wloA + (uint32_t)((mi * 16 * LDT + ks * 16) * 2)); \
            }                                                                 \
            _Pragma("unroll")                                                 \
            for (int ni = 0; ni < 4; ++ni) {                                  \
                uint32_t b4[4];                                               \
                LDSM_X4T(b4, bB + (uint32_t)(ks * 4096) +                     \
                              ((wn64 + (uint32_t)(ni * 16)) ^ xorv));         \
                _Pragma("unroll")                                             \
                for (int mi = 0; mi < 2; ++mi) {                              \
                    MMA_BF16(acc[mi][ni], ahi[mi], b4);                       \
                    MMA_BF16(acc[mi][ni], ahi[mi], b4 + 2);                   \
                    MMA_BF16(acc[mi][ni], alo[mi], b4);                       \
                }                                                             \
            }                                                                 \
        }                                                                     \
    } while (0)

    // ---- prologue: fill buffer 0 ------------------------------------------
    {
        float vA[3][4], vB[3][4];
        float4 wf0[2], wf1[2];
        W_LOAD(wf0, 0, 0);
        W_LOAD(wf1, 0, 2);
        GATHER_HALF(vA, 0, 0);
        GATHER_HALF(vB, 0, 4);
        W_COMMIT(wf0, 0, 0);
        W_COMMIT(wf1, 0, 2);
        COMMIT_HALF(vA, 0, 0, 0);
        COMMIT_HALF(vB, 0, 0, 4);
    }
    __syncthreads();

    // ---- main loop ----------------------------------------------------------
    for (int ch = 0; ch < NCHUNK; ++ch) {
        const int cur = ch & 1;
        const uint32_t bufb = sb + (uint32_t)(cur * BUF_BYTES);
        const int nxt_host = (cur ^ 1) * BUF_BYTES;
        const bool sv = (ch + 1 < NCHUNK);
        const int k0n = (ch + 1) * CHUNK_K;

        float vH[3][4];
        float4 wf[2];

        if (sv) { W_LOAD(wf, k0n, 0); GATHER_HALF(vH, k0n, 0); }
        MMA_HALF(bufb, 0);
        if (sv) { W_COMMIT(wf, nxt_host, 0); COMMIT_HALF(vH, nxt_host, k0n, 0); }

        if (sv) { W_LOAD(wf, k0n, 2); GATHER_HALF(vH, k0n, 4); }
        MMA_HALF(bufb, 2);
        if (sv) { W_COMMIT(wf, nxt_host, 2); COMMIT_HALF(vH, nxt_host, k0n, 4); }

        __syncthreads();
    }

    // ---- epilogue: + bias, float2 stores -----------------------------------
#pragma unroll
    for (int mi = 0; mi < 2; ++mi) {
#pragma unroll
        for (int half = 0; half < 2; ++half) {
            const int o = wm * 32 + mi * 16 + grp + half * 8;
            const float bi = __ldg(bias + o);
            float* po = out + (((size_t)bIdx * 128 + o) << 12) + (h0 << 6);
#pragma unroll
            for (int ni = 0; ni < 4; ++ni) {
                const int n = wn * 32 + ni * 8 + qp * 2;
                float2 v;
                v.x = acc[mi][ni][half * 2 + 0] + bi;
                v.y = acc[mi][ni][half * 2 + 1] + bi;
                *(float2*)(po + n) = v;
            }
        }
    }
}

extern "C" void kernel_launch(void* const* d_in, const int* in_sizes, int n_in,
                              void* d_out, int out_size) {
    const float* x       = (const float*)d_in[0];
    const float* offsets = (const float*)d_in[1];
    const float* mask    = (const float*)d_in[2];
    const float* weight  = (const float*)d_in[3];
    const float* bias    = (const float*)d_in[4];
    float* out = (float*)d_out;

    cudaFuncSetAttribute(dcn_v2_kernel,
                         cudaFuncAttributeMaxDynamicSharedMemorySize, SMEM_BYTES);

    dcn_v2_kernel<<<256, NTHREADS, SMEM_BYTES>>>(x, offsets, mask, weight, bias, out);
}

// round 13
// speedup vs baseline: 1.3462x; 1.0500x over previous
#include <cuda_runtime.h>
#include <cuda_bf16.h>
#include <cstdint>

// DCNv2: fused bilinear gather -> bf16 hi/lo split -> mma.sync m16n8k16 GEMM.
// R13: natural 72-k chunks (8 ch x 9 taps, zero waste), k padded to 80 with
// one-time zeroed tail rows, base-pointer gather addressing (imm offsets).
// CTA: M=128 outputs x N=128 pixels, grid=256, 512 threads, 4x4 warps m32n32.
// 3 MMA passes (hi*hi, hi*lo, lo*hi) accumulate fp32 -> ~fp32 accuracy.

#define NTHREADS 512
#define NCHUNK 16
#define LDT 88                       // W tile row length (bf16), 176B rows

#define T_WHI 0                      // W hi: 128 x 88 bf16 = 22528 B
#define T_WLO 22528
#define T_SHI 45056                  // S hi: 80 rows x 256 B = 20480 B
#define T_SLO 65536
#define BUF_BYTES 86016
#define SMEM_BYTES (2 * BUF_BYTES)   // 172032

#define MMA_BF16(d, a, b)                                                     \
    asm volatile(                                                             \
        "mma.sync.aligned.m16n8k16.row.col.f32.bf16.bf16.f32 "                \
        "{%0,%1,%2,%3}, {%4,%5,%6,%7}, {%8,%9}, {%0,%1,%2,%3};"               \
        : "+f"((d)[0]), "+f"((d)[1]), "+f"((d)[2]), "+f"((d)[3])              \
        : "r"((a)[0]), "r"((a)[1]), "r"((a)[2]), "r"((a)[3]),                 \
          "r"((b)[0]), "r"((b)[1]))

#define LDSM_X4(r, addr)                                                      \
    asm volatile("ldmatrix.sync.aligned.m8n8.x4.shared.b16 {%0,%1,%2,%3}, [%4];" \
                 : "=r"((r)[0]), "=r"((r)[1]), "=r"((r)[2]), "=r"((r)[3])     \
                 : "r"(addr))

#define LDSM_X4T(r, addr)                                                     \
    asm volatile("ldmatrix.sync.aligned.m8n8.x4.trans.shared.b16 {%0,%1,%2,%3}, [%4];" \
                 : "=r"((r)[0]), "=r"((r)[1]), "=r"((r)[2]), "=r"((r)[3])     \
                 : "r"(addr))

__device__ __forceinline__ uint32_t smem_u32(const void* p) {
    uint32_t a;
    asm("{ .reg .u64 t; cvta.to.shared.u64 t, %1; cvt.u32.u64 %0, t; }" : "=r"(a) : "l"(p));
    return a;
}

__global__ void __launch_bounds__(NTHREADS, 1)
dcn_v2_kernel(const float* __restrict__ x,
              const float* __restrict__ offsets,
              const float* __restrict__ mask,
              const float* __restrict__ weight,
              const float* __restrict__ bias,
              float* __restrict__ out) {
    extern __shared__ char smem[];
    const uint32_t sb = smem_u32(smem);

    const int tid  = threadIdx.x;
    const int wid  = tid >> 5;
    const int lane = tid & 31;
    const int grp  = lane >> 2;
    const int qp   = lane & 3;
    const int wm   = wid >> 2;
    const int wn   = wid & 3;

    const int bIdx = blockIdx.x >> 5;
    const int h0   = (blockIdx.x & 31) << 1;
    const float* xp = x + ((size_t)bIdx << 19);

    // ---- one-time zero of padded tail rows (k 72..79 / W k 72..87) -------
#pragma unroll
    for (int r = 0; r < 2; ++r) {
        char* bb = smem + r * BUF_BYTES;
        // S tails: rows 72..79 of each tile (2048 B each)
        ((uint32_t*)(bb + T_SHI + 72 * 256))[tid] = 0;
        ((uint32_t*)(bb + T_SLO + 72 * 256))[tid] = 0;
        // W tails: bytes 144..175 of each of 128 rows
#pragma unroll
        for (int i = tid; i < 1024; i += NTHREADS) {
            const int o = i >> 3, w = i & 7;
            const int off = o * 176 + 144 + w * 4;
            *(uint32_t*)(bb + T_WHI + off) = 0;
            *(uint32_t*)(bb + T_WLO + off) = 0;
        }
    }

    // ---- register-resident bilinear taps ---------------------------------
    const int ntaps = 2 + (tid < 128);
    uint2  tio[3];
    float4 twt[3];
#pragma unroll
    for (int j = 0; j < 3; ++j) {
        tio[j] = make_uint2(0u, 0u);
        twt[j] = make_float4(0.f, 0.f, 0.f, 0.f);
        if (j < ntaps) {
            const int e   = tid + (j << 9);
            const int t   = e >> 7;
            const int pix = e & 127;
            const int h   = h0 + (pix >> 6);
            const int wp  = pix & 63;
            const int ky  = t / 3;
            const int kx  = t - ky * 3;
            const int hw  = (h << 6) + wp;

            const size_t ob = ((size_t)bIdx * 18) << 12;
            const float dy = offsets[ob + ((size_t)(2 * t) << 12) + hw];
            const float dx = offsets[ob + ((size_t)(2 * t + 1) << 12) + hw];
            const float m  = mask[(((size_t)bIdx * 9 + t) << 12) + hw];

            const float py = (float)(h - 1 + ky) + dy;
            const float px = (float)(wp - 1 + kx) + dx;
            const float fy = floorf(py), fx = floorf(px);
            const float ay = py - fy, ax = px - fx;
            const float by = 1.f - ay, bx = 1.f - ax;
            const float fy1 = fy + 1.f, fx1 = fx + 1.f;
            const bool vy0 = (fy  >= 0.f) && (fy  <= 63.f);
            const bool vy1 = (fy1 >= 0.f) && (fy1 <= 63.f);
            const bool vx0 = (fx  >= 0.f) && (fx  <= 63.f);
            const bool vx1 = (fx1 >= 0.f) && (fx1 <= 63.f);
            const int y0 = (int)fminf(fmaxf(fy,  0.f), 63.f);
            const int y1 = (int)fminf(fmaxf(fy1, 0.f), 63.f);
            const int x0 = (int)fminf(fmaxf(fx,  0.f), 63.f);
            const int x1 = (int)fminf(fmaxf(fx1, 0.f), 63.f);
            const unsigned i0 = (unsigned)((y0 << 6) + x0);
            const unsigned i1 = (unsigned)((y0 << 6) + x1);
            const unsigned i2 = (unsigned)((y1 << 6) + x0);
            const unsigned i3 = (unsigned)((y1 << 6) + x1);
            tio[j] = make_uint2(i0 | (i1 << 16), i2 | (i3 << 16));
            twt[j] = make_float4((vy0 && vx0) ? by * bx * m : 0.f,
                                 (vy0 && vx1) ? by * ax * m : 0.f,
                                 (vy1 && vx0) ? ay * bx * m : 0.f,
                                 (vy1 && vx1) ? ay * ax * m : 0.f);
        }
    }

    float acc[2][4][4];
#pragma unroll
    for (int mi = 0; mi < 2; ++mi)
#pragma unroll
        for (int ni = 0; ni < 4; ++ni)
#pragma unroll
            for (int q = 0; q < 4; ++q) acc[mi][ni][q] = 0.f;

    // ---- staging helpers --------------------------------------------------
    // gather 4 channels (U0..U0+3) per owned tap; base ptr + imm offsets
#define GATHER_HALF(V, CB, U0)                                                \
    do {                                                                      \
        const float* qc = xp + ((size_t)(CB) << 12);                          \
        _Pragma("unroll")                                                     \
        for (int j = 0; j < 3; ++j) {                                         \
            if (j < ntaps) {                                                  \
                const float4 w = twt[j];                                      \
                const float* b0 = qc + (tio[j].x & 0xFFFF);                   \
                const float* b1 = qc + (tio[j].x >> 16);                      \
                const float* b2 = qc + (tio[j].y & 0xFFFF);                   \
                const float* b3 = qc + (tio[j].y >> 16);                      \
                _Pragma("unroll")                                             \
                for (int u = 0; u < 4; ++u) {                                 \
                    const int co = ((U0) + u) << 12;                          \
                    V[j][u] = fmaf(w.x, __ldg(b0 + co),                       \
                              fmaf(w.y, __ldg(b1 + co),                       \
                              fmaf(w.z, __ldg(b2 + co),                       \
                                   w.w * __ldg(b3 + co))));                   \
                }                                                             \
            }                                                                 \
        }                                                                     \
    } while (0)

    // convert + store to swizzled k-major S tiles; kl = c*9 + t (all valid)
#define COMMIT_HALF(V, BUFB_HOST, U0)                                         \
    do {                                                                      \
        char* shi = smem + (BUFB_HOST) + T_SHI;                               \
        char* slo = smem + (BUFB_HOST) + T_SLO;                               \
        _Pragma("unroll")                                                     \
        for (int j = 0; j < 3; ++j) {                                         \
            if (j < ntaps) {                                                  \
                const int e    = tid + (j << 9);                              \
                const int t    = e >> 7;                                      \
                const int pix2 = (e & 127) * 2;                               \
                const int tb   = t << 8;                                      \
                const int t4   = t << 4;                                      \
                _Pragma("unroll")                                             \
                for (int u = 0; u < 4; ++u) {                                 \
                    const int c = (U0) + u;                                   \
                    const float v = V[j][u];                                  \
                    const __nv_bfloat16 hb = __float2bfloat16(v);             \
                    const __nv_bfloat16 lb =                                  \
                        __float2bfloat16(v - __bfloat162float(hb));           \
                    const int ad = tb + c * 2304 +                            \
                                   (pix2 ^ ((t4 + (c << 4)) & 0x70));         \
                    *(__nv_bfloat16*)(shi + ad) = hb;                         \
                    *(__nv_bfloat16*)(slo + ad) = lb;                         \
                }                                                             \
            }                                                                 \
        }                                                                     \
    } while (0)

    // W stage: 2304 float4 per chunk (128 o x 18 kq). Group A: it 0-1,
    // group B: it 2-4 (it 4 only for tid<256).
#define W_LOAD_A(WF, K0F)                                                     \
    do {                                                                      \
        _Pragma("unroll")                                                     \
        for (int it = 0; it < 2; ++it) {                                      \
            const int idx4 = tid + it * NTHREADS;                             \
            const int o  = idx4 / 18;                                         \
            const int kq = idx4 - o * 18;                                     \
            WF[it] = __ldg(                                                   \
                (const float4*)(weight + (size_t)o * 1152 + (K0F) + kq * 4)); \
        }                                                                     \
    } while (0)

#define W_LOAD_B(WF, K0F)                                                     \
    do {                                                                      \
        _Pragma("unroll")                                                     \
        for (int it = 2; it < 5; ++it) {                                      \
            if (it < 4 || tid < 256) {                                        \
                const int idx4 = tid + it * NTHREADS;                         \
                const int o  = idx4 / 18;                                     \
                const int kq = idx4 - o * 18;                                 \
                WF[it - 2] = __ldg(                                           \
                    (const float4*)(weight + (size_t)o * 1152 + (K0F) + kq * 4)); \
            }                                                                 \
        }                                                                     \
    } while (0)

#define W_COMMIT_ONE(F, IDX4, DHI, DLO)                                       \
    do {                                                                      \
        const int o  = (IDX4) / 18;                                           \
        const int kq = (IDX4) - o * 18;                                       \
        const float4 f = (F);                                                 \
        __nv_bfloat162 h01 = __floats2bfloat162_rn(f.x, f.y);                 \
        __nv_bfloat162 h23 = __floats2bfloat162_rn(f.z, f.w);                 \
        const float2 g01 = __bfloat1622float2(h01);                           \
        const float2 g23 = __bfloat1622float2(h23);                           \
        __nv_bfloat162 l01 = __floats2bfloat162_rn(f.x - g01.x, f.y - g01.y); \
        __nv_bfloat162 l23 = __floats2bfloat162_rn(f.z - g23.x, f.w - g23.y); \
        const int bo = o * 176 + kq * 8;                                      \
        *(uint2*)((DHI) + bo) = make_uint2(*(uint32_t*)&h01, *(uint32_t*)&h23); \
        *(uint2*)((DLO) + bo) = make_uint2(*(uint32_t*)&l01, *(uint32_t*)&l23); \
    } while (0)

#define W_COMMIT_A(WF, BUFB_HOST)                                             \
    do {                                                                      \
        char* dhi = smem + (BUFB_HOST) + T_WHI;                               \
        char* dlo = smem + (BUFB_HOST) + T_WLO;                               \
        W_COMMIT_ONE(WF[0], tid, dhi, dlo);                                   \
        W_COMMIT_ONE(WF[1], tid + NTHREADS, dhi, dlo);                        \
    } while (0)

#define W_COMMIT_B(WF, BUFB_HOST)                                             \
    do {                                                                      \
        char* dhi = smem + (BUFB_HOST) + T_WHI;                               \
        char* dlo = smem + (BUFB_HOST) + T_WLO;                               \
        W_COMMIT_ONE(WF[0], tid + 2 * NTHREADS, dhi, dlo);                    \
        W_COMMIT_ONE(WF[1], tid + 3 * NTHREADS, dhi, dlo);                    \
        if (tid < 256) W_COMMIT_ONE(WF[2], tid + 4 * NTHREADS, dhi, dlo);     \
    } while (0)

    // ---- MMA lane addressing ----------------------------------------------
    const int lr   = lane >> 3;
    const int lrow = lane & 7;
    const uint32_t a_lane_off =
        (uint32_t)(((wm * 32 + (lr & 1) * 8 + lrow) * LDT + (lr >> 1) * 8) * 2);
    const uint32_t b_lane_const =
        (uint32_t)(((lr & 1) * 8 + lrow) * 256) + (uint32_t)((lr >> 1) ? T_SLO : T_SHI);
    const uint32_t xorv = (uint32_t)(lrow << 4);
    const uint32_t wn64 = (uint32_t)(wn * 64);

#define MMA_PART(BUFB, KS0, KS1)                                              \
    do {                                                                      \
        const uint32_t whiA = (BUFB) + T_WHI + a_lane_off;                    \
        const uint32_t wloA = (BUFB) + T_WLO + a_lane_off;                    \
        const uint32_t bB   = (BUFB) + b_lane_const;                          \
        _Pragma("unroll")                                                     \
        for (int ks = (KS0); ks < (KS1); ++ks) {                              \
            uint32_t ahi[2][4], alo[2][4];                                    \
            _Pragma("unroll")                                                 \
            for (int mi = 0; mi < 2; ++mi) {                                  \
                LDSM_X4(ahi[mi], whiA + (uint32_t)((mi * 16 * LDT + ks * 16) * 2)); \
                LDSM_X4(alo[mi], wloA + (uint32_t)((mi * 16 * LDT + ks * 16) * 2)); \
            }                                                                 \
            _Pragma("unroll")                                                 \
            for (int ni = 0; ni < 4; ++ni) {                                  \
                uint32_t b4[4];                                               \
                LDSM_X4T(b4, bB + (uint32_t)(ks * 4096) +                     \
                              ((wn64 + (uint32_t)(ni * 16)) ^ xorv));         \
                _Pragma("unroll")                                             \
                for (int mi = 0; mi < 2; ++mi) {                              \
                    MMA_BF16(acc[mi][ni], ahi[mi], b4);                       \
                    MMA_BF16(acc[mi][ni], ahi[mi], b4 + 2);                   \
                    MMA_BF16(acc[mi][ni], alo[mi], b4);                       \
                }                                                             \
            }                                                                 \
        }                                                                     \
    } while (0)

    // ---- prologue: fill buffer 0 ------------------------------------------
    {
        float vA[3][4], vB[3][4];
        float4 wfa[2], wfb[3];
        W_LOAD_A(wfa, 0);
        W_LOAD_B(wfb, 0);
        GATHER_HALF(vA, 0, 0);
        GATHER_HALF(vB, 0, 4);
        W_COMMIT_A(wfa, 0);
        W_COMMIT_B(wfb, 0);
        COMMIT_HALF(vA, 0, 0);
        COMMIT_HALF(vB, 0, 4);
    }
    __syncthreads();

    // ---- main loop ----------------------------------------------------------
    for (int ch = 0; ch < NCHUNK; ++ch) {
        const int cur = ch & 1;
        const uint32_t bufb = sb + (uint32_t)(cur * BUF_BYTES);
        const int nxt = (cur ^ 1) * BUF_BYTES;
        const bool sv = (ch + 1 < NCHUNK);
        const int cb  = (ch + 1) * 8;     // channel base of next chunk
        const int k0f = (ch + 1) * 72;    // k float base of next chunk

        float vH[3][4];
        float4 wfa[2], wfb[3];

        if (sv) { W_LOAD_A(wfa, k0f); GATHER_HALF(vH, cb, 0); }
        MMA_PART(bufb, 0, 2);
        if (sv) { W_COMMIT_A(wfa, nxt); COMMIT_HALF(vH, nxt, 0); }

        if (sv) { W_LOAD_B(wfb, k0f); GATHER_HALF(vH, cb, 4); }
        MMA_PART(bufb, 2, 5);
        if (sv) { W_COMMIT_B(wfb, nxt); COMMIT_HALF(vH, nxt, 4); }

        __syncthreads();
    }

    // ---- epilogue: + bias, float2 stores -----------------------------------
#pragma unroll
    for (int mi = 0; mi < 2; ++mi) {
#pragma unroll
        for (int half = 0; half < 2; ++half) {
            const int o = wm * 32 + mi * 16 + grp + half * 8;
            const float bi = __ldg(bias + o);
            float* po = out + (((size_t)bIdx * 128 + o) << 12) + (h0 << 6);
#pragma unroll
            for (int ni = 0; ni < 4; ++ni) {
                const int n = wn * 32 + ni * 8 + qp * 2;
                float2 v;
                v.x = acc[mi][ni][half * 2 + 0] + bi;
                v.y = acc[mi][ni][half * 2 + 1] + bi;
                *(float2*)(po + n) = v;
            }
        }
    }
}

extern "C" void kernel_launch(void* const* d_in, const int* in_sizes, int n_in,
                              void* d_out, int out_size) {
    const float* x       = (const float*)d_in[0];
    const float* offsets = (const float*)d_in[1];
    const float* mask    = (const float*)d_in[2];
    const float* weight  = (const float*)d_in[3];
    const float* bias    = (const float*)d_in[4];
    float* out = (float*)d_out;

    cudaFuncSetAttribute(dcn_v2_kernel,
                         cudaFuncAttributeMaxDynamicSharedMemorySize, SMEM_BYTES);

    dcn_v2_kernel<<<256, NTHREADS, SMEM_BYTES>>>(x, offsets, mask, weight, bias, out);
}